// round 11
// baseline (speedup 1.0000x reference)
#include <cuda_runtime.h>
#include <cuda_bf16.h>

// DDA_PU_loss: loss = sum_pos((rec-dv)^2)*(1-a)/2 + sum_neg((rec-dv)^2)*a/2
// Inputs (metadata order):
//  0: drug_virus_reconstruct  float32 [8192*16384]
//  1: drug_virus              float32 [8192*16384]
//  2: drug_virus_mask         float32 (UNUSED by reference)
//  3: pos_x_index  int32 [524288]   (JAX x64 disabled: astype(int64) -> int32)
//  4: pos_y_index  int32 [524288]
//  5: neg_x_index  int32 [2097152]
//  6: neg_y_index  int32 [2097152]
//  7: alpha        float32 [1]
// Output: float32 scalar.

#define KP_N_POS   524288
#define KP_LOG_NV  14          // N_VIRUS = 16384 = 1<<14
#define KP_BLOCKS  2048
#define KP_THREADS 256
// KP_BLOCKS*KP_THREADS = 524288 threads; thread t handles pos[t] and
// neg[t + k*524288], k=0..3  -> exact coverage of both index sets.

__device__ double g_partials[KP_BLOCKS];

__global__ __launch_bounds__(KP_THREADS)
void dda_gather_sq_kernel(const float* __restrict__ rec,
                          const float* __restrict__ dv,
                          const int* __restrict__ px,
                          const int* __restrict__ py,
                          const int* __restrict__ nx,
                          const int* __restrict__ ny,
                          const float* __restrict__ alpha_p)
{
    const unsigned t = blockIdx.x * KP_THREADS + threadIdx.x;  // 0..524287

    const float alpha = __ldg(alpha_p);
    const float wp = (1.0f - alpha) * 0.5f;
    const float wn = alpha * 0.5f;

    // --- front-batch all index loads (coalesced) ---
    unsigned off0 = ((unsigned)__ldg(&px[t]) << KP_LOG_NV)
                  +  (unsigned)__ldg(&py[t]);
    unsigned offs[4];
#pragma unroll
    for (int k = 0; k < 4; k++) {
        unsigned j = t + (unsigned)k * KP_N_POS;
        offs[k] = ((unsigned)__ldg(&nx[j]) << KP_LOG_NV)
                +  (unsigned)__ldg(&ny[j]);
    }

    // --- 10 independent random-coordinate data loads (high MLP) ---
    float d0  = __ldg(rec + off0) - __ldg(dv + off0);
    float ns  = 0.0f;
#pragma unroll
    for (int k = 0; k < 4; k++) {
        float d = __ldg(rec + offs[k]) - __ldg(dv + offs[k]);
        ns = fmaf(d, d, ns);
    }
    float sum = fmaf(wp * d0, d0, wn * ns);

    // --- block reduce (fp32 tree over ~1280 O(1)-magnitude terms) ---
#pragma unroll
    for (int o = 16; o > 0; o >>= 1)
        sum += __shfl_down_sync(0xffffffffu, sum, o);

    __shared__ float warp_sums[KP_THREADS / 32];
    const int lane = threadIdx.x & 31;
    const int wrp  = threadIdx.x >> 5;
    if (lane == 0) warp_sums[wrp] = sum;
    __syncthreads();

    if (wrp == 0) {
        float v = (lane < KP_THREADS / 32) ? warp_sums[lane] : 0.0f;
#pragma unroll
        for (int o = 4; o > 0; o >>= 1)
            v += __shfl_down_sync(0xffu, v, o);
        if (lane == 0)
            g_partials[blockIdx.x] = (double)v;  // every block writes its slot
    }
}

__global__ __launch_bounds__(1024)
void dda_final_reduce_kernel(float* __restrict__ out)
{
    const int t = threadIdx.x;  // 1024 threads, 2048 partials
    double v = g_partials[t] + g_partials[t + 1024];

#pragma unroll
    for (int o = 16; o > 0; o >>= 1)
        v += __shfl_down_sync(0xffffffffu, v, o);

    __shared__ double warp_sums[32];
    const int lane = t & 31;
    const int wrp  = t >> 5;
    if (lane == 0) warp_sums[wrp] = v;
    __syncthreads();

    if (wrp == 0) {
        double s = warp_sums[lane];  // exactly 32 warps
#pragma unroll
        for (int o = 16; o > 0; o >>= 1)
            s += __shfl_down_sync(0xffffffffu, s, o);
        if (lane == 0)
            out[0] = (float)s;
    }
}

extern "C" void kernel_launch(void* const* d_in, const int* in_sizes, int n_in,
                              void* d_out, int out_size)
{
    const float* rec     = (const float*)d_in[0];
    const float* dv      = (const float*)d_in[1];
    // d_in[2] = mask, unused (reference ignores it)
    const int*   px      = (const int*)d_in[3];
    const int*   py      = (const int*)d_in[4];
    const int*   nx      = (const int*)d_in[5];
    const int*   ny      = (const int*)d_in[6];
    const float* alpha_p = (const float*)d_in[7];
    float*       out     = (float*)d_out;

    dda_gather_sq_kernel<<<KP_BLOCKS, KP_THREADS>>>(rec, dv, px, py, nx, ny, alpha_p);
    dda_final_reduce_kernel<<<1, 1024>>>(out);
}